// round 7
// baseline (speedup 1.0000x reference)
#include <cuda_runtime.h>
#include <cuda_bf16.h>
#include <math_constants.h>
#include <stdint.h>

// Problem constants
#define B 4
#define N 2048
#define DIM 1024
#define HEADS 8
#define DQK 64
#define DV 128
#define MAX_POS 10
#define SCALE 0.125f   // 64^-0.5
#define BN_ROWS (B*N)  // 8192

// -------- scratch (device globals: allocation-free) --------
__device__ float g_qk[(size_t)BN_ROWS * DIM];  // q | k packed: [8192, 1024]
__device__ float g_v [(size_t)BN_ROWS * DIM];  // [8192, 1024]
__device__ float g_ao[(size_t)BN_ROWS * DIM];  // attention output [8192, 1024]
// Transposed + bf16-split weights: rows 0..1023 = W_qk^T, 1024..2047 = W_v^T, 2048..3071 = W_out^T
__device__ __align__(16) __nv_bfloat16 g_Wh[(size_t)3072 * 1024];
__device__ __align__(16) __nv_bfloat16 g_Wl[(size_t)3072 * 1024];

// ---------------- helpers ----------------
__device__ __forceinline__ void mma_bf16(float c[4], const uint32_t a[4], const uint32_t b[2]) {
    asm volatile(
        "mma.sync.aligned.m16n8k16.row.col.f32.bf16.bf16.f32 "
        "{%0,%1,%2,%3}, {%4,%5,%6,%7}, {%8,%9}, {%0,%1,%2,%3};"
        : "+f"(c[0]), "+f"(c[1]), "+f"(c[2]), "+f"(c[3])
        : "r"(a[0]), "r"(a[1]), "r"(a[2]), "r"(a[3]), "r"(b[0]), "r"(b[1]));
}

// pack two consecutive floats into bf16x2 hi and lo (residual) words
__device__ __forceinline__ void bf16_split2(float a, float b, uint32_t& h, uint32_t& l) {
    __nv_bfloat162 hp, lp;
    hp.x = __float2bfloat16(a); hp.y = __float2bfloat16(b);
    lp.x = __float2bfloat16(a - __bfloat162float(hp.x));
    lp.y = __float2bfloat16(b - __bfloat162float(hp.y));
    h = *reinterpret_cast<uint32_t*>(&hp);
    l = *reinterpret_cast<uint32_t*>(&lp);
}

// ======================= weight prep: transpose + bf16 split =======================
__global__ __launch_bounds__(256)
void wprep_kernel(const float* __restrict__ W,
                  __nv_bfloat16* __restrict__ Wh, __nv_bfloat16* __restrict__ Wl)
{
    __shared__ float t[32][33];
    const int tx = threadIdx.x & 31, ty = threadIdx.x >> 5;  // 32 x 8
    const int n0 = blockIdx.x * 32, k0 = blockIdx.y * 32;
    #pragma unroll
    for (int i = 0; i < 4; i++)
        t[ty + 8 * i][tx] = W[(size_t)(k0 + ty + 8 * i) * 1024 + n0 + tx];
    __syncthreads();
    #pragma unroll
    for (int i = 0; i < 4; i++) {
        float x = t[tx][ty + 8 * i];
        __nv_bfloat16 h = __float2bfloat16(x);
        __nv_bfloat16 l = __float2bfloat16(x - __bfloat162float(h));
        size_t o = (size_t)(n0 + ty + 8 * i) * 1024 + k0 + tx;
        Wh[o] = h; Wl[o] = l;
    }
}

// ======================= bf16 3-term tensor-core GEMM =======================
// C[M=128 x N=128] per CTA = A[128,K] @ Wt[N,K]^T (+bias).
// 8 warps (2x4), warp tile 64x32, mma.m16n8k16.bf16, K stepped 16/iter, double-buffered.
// smem layout: pair-packed uint32 [row][kpair], row stride 12 words (conflict-free).
#define RSTRIDE 12
#define TBUF (128 * RSTRIDE)                 // 1536 words per tile buffer
#define GEMM_SMEM_WORDS (8 * TBUF)           // Ah,Al,Bh,Bl x 2 buffers
#define GEMM_SMEM_BYTES (GEMM_SMEM_WORDS * 4)  // 49152

__global__ __launch_bounds__(256, 2)
void gemm_bf3_kernel(const float* __restrict__ A,
                     const __nv_bfloat16* __restrict__ WtH,
                     const __nv_bfloat16* __restrict__ WtL,
                     const float* __restrict__ bias,
                     float* __restrict__ C0, float* __restrict__ C1, int nsplit)
{
    extern __shared__ uint32_t smg[];
    uint32_t* AsH = smg;                 // [2][TBUF]
    uint32_t* AsL = smg + 2 * TBUF;
    uint32_t* BsH = smg + 4 * TBUF;
    uint32_t* BsL = smg + 6 * TBUF;

    const int tid  = threadIdx.x;
    const int lane = tid & 31;
    const int w    = tid >> 5;
    const int wm   = w >> 2;             // 0..1
    const int wn   = w & 3;              // 0..3
    const int g    = lane >> 2;          // 0..7
    const int r    = lane & 3;           // 0..3

    const int bx = blockIdx.x, by = blockIdx.y;
    float* C = C0;
    int cb = bx * 128;
    if (bx >= nsplit) { C = C1; cb = (bx - nsplit) * 128; }

    const float* Ab = A + (size_t)(by * 128) * 1024;
    const __nv_bfloat16* WhB = WtH + (size_t)(bx * 128) * 1024;
    const __nv_bfloat16* WlB = WtL + (size_t)(bx * 128) * 1024;

    // staging mapping: row = tid & 127 (phase-conflict-free STS), half = tid >> 7
    const int sRow = tid & 127;
    const int sC8  = (tid >> 7) * 8;     // float/bf16 column offset within k16
    const int sKP  = (tid >> 7) * 4;     // kpair offset

    float acc[4][4][4];
    #pragma unroll
    for (int mt = 0; mt < 4; mt++)
        #pragma unroll
        for (int nt = 0; nt < 4; nt++)
            #pragma unroll
            for (int i = 0; i < 4; i++) acc[mt][nt][i] = 0.f;

    float4 aR0, aR1;     // 8 floats of A row
    uint4  bRh, bRl;     // 8 bf16 h + 8 bf16 l of B row

    #define LDG_T(k0)                                                            \
        do {                                                                     \
            const float* asrc = Ab + (size_t)sRow * 1024 + (k0) + sC8;           \
            aR0 = *(const float4*)asrc;                                          \
            aR1 = *(const float4*)(asrc + 4);                                    \
            size_t bo = (size_t)sRow * 1024 + (k0) + sC8;                        \
            bRh = *(const uint4*)(WhB + bo);                                     \
            bRl = *(const uint4*)(WlB + bo);                                     \
        } while (0)

    #define STS_T(buf)                                                           \
        do {                                                                     \
            uint32_t h0, h1, h2, h3, l0, l1, l2, l3;                             \
            bf16_split2(aR0.x, aR0.y, h0, l0);                                   \
            bf16_split2(aR0.z, aR0.w, h1, l1);                                   \
            bf16_split2(aR1.x, aR1.y, h2, l2);                                   \
            bf16_split2(aR1.z, aR1.w, h3, l3);                                   \
            uint32_t off = (buf) * TBUF + sRow * RSTRIDE + sKP;                  \
            *(uint4*)&AsH[off] = make_uint4(h0, h1, h2, h3);                     \
            *(uint4*)&AsL[off] = make_uint4(l0, l1, l2, l3);                     \
            *(uint4*)&BsH[off] = bRh;                                            \
            *(uint4*)&BsL[off] = bRl;                                            \
        } while (0)

    LDG_T(0);
    STS_T(0);
    __syncthreads();

    for (int it = 0; it < 64; it++) {
        const int cur = it & 1;
        if (it + 1 < 64) LDG_T((it + 1) * 16);

        const uint32_t* Ah = AsH + cur * TBUF;
        const uint32_t* Al = AsL + cur * TBUF;
        const uint32_t* Bh = BsH + cur * TBUF;
        const uint32_t* Bl = BsL + cur * TBUF;

        uint32_t bh[4][2], bl[4][2];
        #pragma unroll
        for (int nt = 0; nt < 4; nt++) {
            int n0 = (wn * 32 + nt * 8 + g) * RSTRIDE;
            bh[nt][0] = Bh[n0 + r];
            bh[nt][1] = Bh[n0 + r + 4];
            bl[nt][0] = Bl[n0 + r];
            bl[nt][1] = Bl[n0 + r + 4];
        }
        #pragma unroll
        for (int mt = 0; mt < 4; mt++) {
            int m0 = (wm * 64 + mt * 16 + g) * RSTRIDE;
            int m8 = m0 + 8 * RSTRIDE;
            uint32_t ah[4], al[4];
            ah[0] = Ah[m0 + r];     ah[1] = Ah[m8 + r];
            ah[2] = Ah[m0 + r + 4]; ah[3] = Ah[m8 + r + 4];
            al[0] = Al[m0 + r];     al[1] = Al[m8 + r];
            al[2] = Al[m0 + r + 4]; al[3] = Al[m8 + r + 4];
            #pragma unroll
            for (int nt = 0; nt < 4; nt++) {
                mma_bf16(acc[mt][nt], ah, bl[nt]);
                mma_bf16(acc[mt][nt], al, bh[nt]);
                mma_bf16(acc[mt][nt], ah, bh[nt]);
            }
        }

        if (it + 1 < 64) STS_T(cur ^ 1);
        __syncthreads();
    }

    // ---- epilogue ----
    #pragma unroll
    for (int mt = 0; mt < 4; mt++) {
        int row0 = by * 128 + wm * 64 + mt * 16 + g;
        #pragma unroll
        for (int nt = 0; nt < 4; nt++) {
            int col = cb + wn * 32 + nt * 8 + r * 2;
            float b0 = 0.f, b1 = 0.f;
            if (bias != nullptr) { b0 = bias[col]; b1 = bias[col + 1]; }
            float2 v0 = make_float2(acc[mt][nt][0] + b0, acc[mt][nt][1] + b1);
            float2 v1 = make_float2(acc[mt][nt][2] + b0, acc[mt][nt][3] + b1);
            *(float2*)(C + (size_t)row0 * 1024 + col)       = v0;
            *(float2*)(C + (size_t)(row0 + 8) * 1024 + col) = v1;
        }
    }
}

// ======================= Tensor-core flash attention (unchanged) =======================
__device__ __forceinline__ uint32_t f2tf32(float x) {
    uint32_t r;
    asm("cvt.rna.tf32.f32 %0, %1;" : "=r"(r) : "f"(x));
    return r;
}
__device__ __forceinline__ void mma_tf32(float c[4], const uint32_t a[4], const uint32_t b[2]) {
    asm volatile(
        "mma.sync.aligned.m16n8k8.row.col.f32.tf32.tf32.f32 "
        "{%0,%1,%2,%3}, {%4,%5,%6,%7}, {%8,%9}, {%0,%1,%2,%3};"
        : "+f"(c[0]), "+f"(c[1]), "+f"(c[2]), "+f"(c[3])
        : "r"(a[0]), "r"(a[1]), "r"(a[2]), "r"(a[3]), "r"(b[0]), "r"(b[1]));
}

#define AKT 64
#define QT  64
#define QS_STRIDE 68
#define KS_STRIDE 68
#define VS_STRIDE 136

#define A_QS 0
#define A_KS (A_QS + QT*QS_STRIDE)
#define A_VS (A_KS + AKT*KS_STRIDE)
#define A_CV (A_VS + AKT*VS_STRIDE)
#define A_TOT (A_CV + 32)
#define ATTN_SMEM_BYTES (A_TOT * 4)

__global__ __launch_bounds__(128, 3)
void attn_tc_kernel(const float* __restrict__ qk, const float* __restrict__ vbuf,
                    const float* __restrict__ conv, float* __restrict__ out)
{
    extern __shared__ uint32_t smu[];
    uint32_t* Qs = smu + A_QS;
    uint32_t* Ks = smu + A_KS;
    uint32_t* Vs = smu + A_VS;
    float*    Cv = (float*)(smu + A_CV);

    const int tid  = threadIdx.x;
    const int lane = tid & 31;
    const int w    = tid >> 5;
    const int g    = lane >> 2;
    const int r    = lane & 3;
    const int h    = blockIdx.y;
    const int b    = blockIdx.z;
    const int i0   = blockIdx.x * QT;
    const uint32_t full = 0xffffffffu;

    if (tid < 2 * MAX_POS + 1) Cv[tid] = conv[h * (2 * MAX_POS + 1) + tid];

    for (int t = tid; t < QT * 16; t += 128) {
        int row = t >> 4, c4 = (t & 15) << 2;
        float4 v = *(const float4*)(qk + ((size_t)(b * N + i0 + row)) * DIM + h * DQK + c4);
        uint4 u;
        u.x = f2tf32(v.x); u.y = f2tf32(v.y); u.z = f2tf32(v.z); u.w = f2tf32(v.w);
        *(uint4*)&Qs[row * QS_STRIDE + c4] = u;
    }

    float m_lo = -CUDART_INF_F, m_hi = -CUDART_INF_F;
    float l_lo = 0.f, l_hi = 0.f;
    float oacc[8][2][4];
    #pragma unroll
    for (int mt = 0; mt < 8; mt++)
        #pragma unroll
        for (int nt = 0; nt < 2; nt++)
            #pragma unroll
            for (int i = 0; i < 4; i++) oacc[mt][nt][i] = 0.f;

    const int ilo = i0 + w * 16 + g;
    const int ihi = ilo + 8;
    const int srcA = (lane & ~3) | (r >> 1);
    const int srcB = srcA + 2;
    const bool pr  = (r & 1);

    for (int j0 = 0; j0 < N; j0 += AKT) {
        for (int t = tid; t < AKT * 16; t += 128) {
            int row = t >> 4, c4 = (t & 15) << 2;
            float4 v = *(const float4*)(qk + ((size_t)(b * N + j0 + row)) * DIM
                                         + HEADS * DQK + h * DQK + c4);
            uint4 u;
            u.x = f2tf32(v.x); u.y = f2tf32(v.y); u.z = f2tf32(v.z); u.w = f2tf32(v.w);
            *(uint4*)&Ks[row * KS_STRIDE + c4] = u;
        }
        for (int t = tid; t < AKT * 32; t += 128) {
            int row = t >> 5, c4 = (t & 31) << 2;
            float4 v = *(const float4*)(vbuf + ((size_t)(b * N + j0 + row)) * DIM + h * DV + c4);
            uint4 u;
            u.x = f2tf32(v.x); u.y = f2tf32(v.y); u.z = f2tf32(v.z); u.w = f2tf32(v.w);
            *(uint4*)&Vs[row * VS_STRIDE + c4] = u;
        }
        __syncthreads();

        float sacc[8][4];
        #pragma unroll
        for (int nt = 0; nt < 8; nt++)
            #pragma unroll
            for (int i = 0; i < 4; i++) sacc[nt][i] = 0.f;

        const int qrow = w * 16 + g;
        #pragma unroll
        for (int kt = 0; kt < 8; kt++) {
            uint32_t qa[4];
            qa[0] = Qs[ qrow      * QS_STRIDE + kt * 8 + r];
            qa[1] = Qs[(qrow + 8) * QS_STRIDE + kt * 8 + r];
            qa[2] = Qs[ qrow      * QS_STRIDE + kt * 8 + r + 4];
            qa[3] = Qs[(qrow + 8) * QS_STRIDE + kt * 8 + r + 4];
            #pragma unroll
            for (int nt = 0; nt < 8; nt++) {
                uint32_t bf[2];
                bf[0] = Ks[(nt * 8 + g) * KS_STRIDE + kt * 8 + r];
                bf[1] = Ks[(nt * 8 + g) * KS_STRIDE + kt * 8 + r + 4];
                mma_tf32(sacc[nt], qa, bf);
            }
        }

        float rx_lo = -CUDART_INF_F, rx_hi = -CUDART_INF_F;
        #pragma unroll
        for (int nt = 0; nt < 8; nt++) {
            int j = j0 + nt * 8 + 2 * r;
            int d00 = min(max(j     - ilo, -MAX_POS), MAX_POS) + MAX_POS;
            int d01 = min(max(j + 1 - ilo, -MAX_POS), MAX_POS) + MAX_POS;
            int d10 = min(max(j     - ihi, -MAX_POS), MAX_POS) + MAX_POS;
            int d11 = min(max(j + 1 - ihi, -MAX_POS), MAX_POS) + MAX_POS;
            sacc[nt][0] = sacc[nt][0] * SCALE + Cv[d00];
            sacc[nt][1] = sacc[nt][1] * SCALE + Cv[d01];
            sacc[nt][2] = sacc[nt][2] * SCALE + Cv[d10];
            sacc[nt][3] = sacc[nt][3] * SCALE + Cv[d11];
            rx_lo = fmaxf(rx_lo, fmaxf(sacc[nt][0], sacc[nt][1]));
            rx_hi = fmaxf(rx_hi, fmaxf(sacc[nt][2], sacc[nt][3]));
        }
        rx_lo = fmaxf(rx_lo, __shfl_xor_sync(full, rx_lo, 1));
        rx_lo = fmaxf(rx_lo, __shfl_xor_sync(full, rx_lo, 2));
        rx_hi = fmaxf(rx_hi, __shfl_xor_sync(full, rx_hi, 1));
        rx_hi = fmaxf(rx_hi, __shfl_xor_sync(full, rx_hi, 2));

        float mn_lo = fmaxf(m_lo, rx_lo);
        float mn_hi = fmaxf(m_hi, rx_hi);
        float al_lo = __expf(m_lo - mn_lo);
        float al_hi = __expf(m_hi - mn_hi);
        m_lo = mn_lo; m_hi = mn_hi;

        uint32_t Pf[8][4];
        float ls_lo = 0.f, ls_hi = 0.f;
        #pragma unroll
        for (int nt = 0; nt < 8; nt++) {
            float p0 = __expf(sacc[nt][0] - m_lo);
            float p1 = __expf(sacc[nt][1] - m_lo);
            float p2 = __expf(sacc[nt][2] - m_hi);
            float p3 = __expf(sacc[nt][3] - m_hi);
            ls_lo += p0 + p1;
            ls_hi += p2 + p3;
            Pf[nt][0] = f2tf32(p0); Pf[nt][1] = f2tf32(p1);
            Pf[nt][2] = f2tf32(p2); Pf[nt][3] = f2tf32(p3);
        }
        l_lo = l_lo * al_lo + ls_lo;
        l_hi = l_hi * al_hi + ls_hi;

        float aq0  = __shfl_sync(full, al_lo, 8 * r);
        float aq1  = __shfl_sync(full, al_lo, 8 * r + 4);
        float aq0h = __shfl_sync(full, al_hi, 8 * r);
        float aq1h = __shfl_sync(full, al_hi, 8 * r + 4);
        #pragma unroll
        for (int mt = 0; mt < 8; mt++) {
            oacc[mt][0][0] *= aq0;  oacc[mt][0][1] *= aq1;
            oacc[mt][0][2] *= aq0;  oacc[mt][0][3] *= aq1;
            oacc[mt][1][0] *= aq0h; oacc[mt][1][1] *= aq1h;
            oacc[mt][1][2] *= aq0h; oacc[mt][1][3] *= aq1h;
        }

        #pragma unroll
        for (int kt = 0; kt < 8; kt++) {
            uint32_t s0 = __shfl_sync(full, Pf[kt][0], srcA);
            uint32_t s1 = __shfl_sync(full, Pf[kt][1], srcA);
            uint32_t t0 = __shfl_sync(full, Pf[kt][0], srcB);
            uint32_t t1 = __shfl_sync(full, Pf[kt][1], srcB);
            uint32_t bl2[2];
            bl2[0] = pr ? s1 : s0;
            bl2[1] = pr ? t1 : t0;
            uint32_t s2 = __shfl_sync(full, Pf[kt][2], srcA);
            uint32_t s3 = __shfl_sync(full, Pf[kt][3], srcA);
            uint32_t t2 = __shfl_sync(full, Pf[kt][2], srcB);
            uint32_t t3 = __shfl_sync(full, Pf[kt][3], srcB);
            uint32_t bh2[2];
            bh2[0] = pr ? s3 : s2;
            bh2[1] = pr ? t3 : t2;
            #pragma unroll
            for (int mt = 0; mt < 8; mt++) {
                uint32_t vf[4];
                vf[0] = Vs[(kt * 8 + r)     * VS_STRIDE + mt * 16 + g];
                vf[1] = Vs[(kt * 8 + r)     * VS_STRIDE + mt * 16 + 8 + g];
                vf[2] = Vs[(kt * 8 + r + 4) * VS_STRIDE + mt * 16 + g];
                vf[3] = Vs[(kt * 8 + r + 4) * VS_STRIDE + mt * 16 + 8 + g];
                mma_tf32(oacc[mt][0], vf, bl2);
                mma_tf32(oacc[mt][1], vf, bh2);
            }
        }
        __syncthreads();
    }

    l_lo += __shfl_xor_sync(full, l_lo, 1);
    l_lo += __shfl_xor_sync(full, l_lo, 2);
    l_hi += __shfl_xor_sync(full, l_hi, 1);
    l_hi += __shfl_xor_sync(full, l_hi, 2);
    float inv_lo = 1.f / l_lo;
    float inv_hi = 1.f / l_hi;
    float iq0  = __shfl_sync(full, inv_lo, 8 * r);
    float iq1  = __shfl_sync(full, inv_lo, 8 * r + 4);
    float iq0h = __shfl_sync(full, inv_hi, 8 * r);
    float iq1h = __shfl_sync(full, inv_hi, 8 * r + 4);

    const size_t rbase = (size_t)(b * N + i0 + w * 16);
    #pragma unroll
    for (int mt = 0; mt < 8; mt++) {
        int dcol = h * DV + mt * 16 + g;
        out[(rbase + 2 * r    ) * DIM + dcol    ] = oacc[mt][0][0] * iq0;
        out[(rbase + 2 * r + 1) * DIM + dcol    ] = oacc[mt][0][1] * iq1;
        out[(rbase + 2 * r    ) * DIM + dcol + 8] = oacc[mt][0][2] * iq0;
        out[(rbase + 2 * r + 1) * DIM + dcol + 8] = oacc[mt][0][3] * iq1;
        out[(rbase + 8 + 2 * r    ) * DIM + dcol    ] = oacc[mt][1][0] * iq0h;
        out[(rbase + 8 + 2 * r + 1) * DIM + dcol    ] = oacc[mt][1][1] * iq1h;
        out[(rbase + 8 + 2 * r    ) * DIM + dcol + 8] = oacc[mt][1][2] * iq0h;
        out[(rbase + 8 + 2 * r + 1) * DIM + dcol + 8] = oacc[mt][1][3] * iq1h;
    }
}

// ======================= launch =======================
extern "C" void kernel_launch(void* const* d_in, const int* in_sizes, int n_in,
                              void* d_out, int out_size)
{
    const float* x     = (const float*)d_in[0];
    // d_in[1] = mask (unused by the reference)
    const float* W_qk  = (const float*)d_in[2];
    const float* W_v   = (const float*)d_in[3];
    const float* W_out = (const float*)d_in[4];
    const float* b_out = (const float*)d_in[5];
    const float* conv  = (const float*)d_in[6];
    float* out = (float*)d_out;

    float *qk_p, *v_p, *ao_p;
    cudaGetSymbolAddress((void**)&qk_p, g_qk);
    cudaGetSymbolAddress((void**)&v_p,  g_v);
    cudaGetSymbolAddress((void**)&ao_p, g_ao);
    __nv_bfloat16 *wh_p, *wl_p;
    cudaGetSymbolAddress((void**)&wh_p, g_Wh);
    cudaGetSymbolAddress((void**)&wl_p, g_Wl);

    cudaFuncSetAttribute(gemm_bf3_kernel, cudaFuncAttributeMaxDynamicSharedMemorySize,
                         GEMM_SMEM_BYTES);
    cudaFuncSetAttribute(attn_tc_kernel, cudaFuncAttributeMaxDynamicSharedMemorySize,
                         ATTN_SMEM_BYTES);

    // 0) prep: transpose + bf16-split all three weights
    dim3 wgrid(32, 32);
    wprep_kernel<<<wgrid, 256>>>(W_qk,  wh_p,                      wl_p);
    wprep_kernel<<<wgrid, 256>>>(W_v,   wh_p + (size_t)1024*1024,  wl_p + (size_t)1024*1024);
    wprep_kernel<<<wgrid, 256>>>(W_out, wh_p + (size_t)2048*1024,  wl_p + (size_t)2048*1024);

    // 1+2) fused qkv: bx 0..7 -> g_qk, bx 8..15 -> g_v (Wt rows 1024..2047)
    dim3 qkv_grid(16, 64);
    gemm_bf3_kernel<<<qkv_grid, 256, GEMM_SMEM_BYTES>>>(
        x, wh_p, wl_p, nullptr, qk_p, v_p, 8);

    // 3) attention -> g_ao
    dim3 attn_grid(N / QT, HEADS, B);   // (32, 8, 4)
    attn_tc_kernel<<<attn_grid, 128, ATTN_SMEM_BYTES>>>(qk_p, v_p, conv, ao_p);

    // 4) out = g_ao @ W_out + b_out
    dim3 out_grid(8, 64);
    gemm_bf3_kernel<<<out_grid, 256, GEMM_SMEM_BYTES>>>(
        ao_p, wh_p + (size_t)2048*1024, wl_p + (size_t)2048*1024, b_out, out, out, 8);
}

// round 8
// speedup vs baseline: 1.0470x; 1.0470x over previous
#include <cuda_runtime.h>
#include <math_constants.h>
#include <stdint.h>

// Problem constants
#define B 4
#define N 2048
#define DIM 1024
#define HEADS 8
#define DQK 64
#define DV 128
#define MAX_POS 10
#define SCALE 0.125f   // 64^-0.5
#define BN_ROWS (B*N)  // 8192

// -------- scratch (device globals: allocation-free) --------
__device__ float g_qk[(size_t)BN_ROWS * DIM];  // q | k packed: [8192, 1024]
__device__ float g_v [(size_t)BN_ROWS * DIM];  // [8192, 1024]
__device__ float g_ao[(size_t)BN_ROWS * DIM];  // attention output [8192, 1024]

// ---------------- tf32 helpers ----------------
__device__ __forceinline__ uint32_t f2tf32(float x) {
    uint32_t r;
    asm("cvt.rna.tf32.f32 %0, %1;" : "=r"(r) : "f"(x));
    return r;
}

__device__ __forceinline__ void mma_tf32(float c[4], const uint32_t a[4], const uint32_t b[2]) {
    asm volatile(
        "mma.sync.aligned.m16n8k8.row.col.f32.tf32.tf32.f32 "
        "{%0,%1,%2,%3}, {%4,%5,%6,%7}, {%8,%9}, {%0,%1,%2,%3};"
        : "+f"(c[0]), "+f"(c[1]), "+f"(c[2]), "+f"(c[3])
        : "r"(a[0]), "r"(a[1]), "r"(a[2]), "r"(a[3]), "r"(b[0]), "r"(b[1]));
}

// ======================= 2xTF32 tensor-core GEMM, double-buffered =======================
// C = A @ Bm (+bias). Result = tf32(A) @ B exactly (B split hi/lo).
// CTA tile 128x128x16, 8 warps (2x4), warp tile 64x32.
#define GBM 128
#define GBN 128
#define GBK 16
#define ASTRIDE 20
#define BSTRIDE 136
#define A_BUF (GBM*ASTRIDE)                   // 2560 words
#define B_BUF (GBK*BSTRIDE)                   // 2176 words
#define GEMM_SMEM_WORDS (2*A_BUF + 4*B_BUF)   // 13824 words
#define GEMM_SMEM_BYTES (GEMM_SMEM_WORDS*4)   // 55296 bytes

__global__ __launch_bounds__(256, 2)
void gemm2x_kernel(const float* __restrict__ A,
                   const float* __restrict__ B0, const float* __restrict__ B1,
                   const float* __restrict__ bias,
                   float* __restrict__ C0, float* __restrict__ C1,
                   int nx, int M, int Nn, int K)
{
    extern __shared__ uint32_t smg[];
    uint32_t* AsT = smg;                      // [2][A_BUF]  tf32(A)
    uint32_t* BsH = smg + 2 * A_BUF;          // [2][B_BUF]
    uint32_t* BsL = smg + 2 * A_BUF + 2 * B_BUF;

    const int tid  = threadIdx.x;
    const int lane = tid & 31;
    const int w    = tid >> 5;
    const int wm   = w >> 2;
    const int wn   = w & 3;
    const int g    = lane >> 2;
    const int r    = lane & 3;

    int bx = blockIdx.x;
    const int by = blockIdx.y;
    const float* Bm = B0;
    float* C = C0;
    if (bx >= nx) { Bm = B1; C = C1; bx -= nx; }

    const float* Ablk = A  + (size_t)(by * GBM) * K;
    const float* Bblk = Bm + (size_t)(bx * GBN);

    const int aRow = tid >> 2;           // 0..63 (+64 second pass)
    const int aC4  = (tid & 3) << 2;
    const int bRow = tid >> 5;           // 0..7 (+8 second pass)
    const int bC4  = (tid & 31) << 2;

    float acc[4][4][4];
    #pragma unroll
    for (int mt = 0; mt < 4; mt++)
        #pragma unroll
        for (int nt = 0; nt < 4; nt++)
            #pragma unroll
            for (int i = 0; i < 4; i++) acc[mt][nt][i] = 0.f;

    float4 aR0, aR1, bR0, bR1;   // register staging for next k-tile

    #define LDG_TILE(k0)                                                          \
        do {                                                                      \
            aR0 = *(const float4*)(Ablk + (size_t)aRow * K + (k0) + aC4);         \
            aR1 = *(const float4*)(Ablk + (size_t)(aRow + 64) * K + (k0) + aC4);  \
            bR0 = *(const float4*)(Bblk + (size_t)((k0) + bRow) * Nn + bC4);      \
            bR1 = *(const float4*)(Bblk + (size_t)((k0) + bRow + 8) * Nn + bC4);  \
        } while (0)

    #define STS_TILE(buf)                                                         \
        do {                                                                      \
            uint32_t* At = AsT + (buf) * A_BUF;                                   \
            uint32_t* Bh = BsH + (buf) * B_BUF;                                   \
            uint32_t* Bl = BsL + (buf) * B_BUF;                                   \
            uint4 u;                                                              \
            u.x = f2tf32(aR0.x); u.y = f2tf32(aR0.y);                             \
            u.z = f2tf32(aR0.z); u.w = f2tf32(aR0.w);                             \
            *(uint4*)&At[aRow * ASTRIDE + aC4] = u;                               \
            u.x = f2tf32(aR1.x); u.y = f2tf32(aR1.y);                             \
            u.z = f2tf32(aR1.z); u.w = f2tf32(aR1.w);                             \
            *(uint4*)&At[(aRow + 64) * ASTRIDE + aC4] = u;                        \
            uint4 uh, ul;                                                         \
            uh.x = f2tf32(bR0.x); ul.x = f2tf32(bR0.x - __uint_as_float(uh.x));   \
            uh.y = f2tf32(bR0.y); ul.y = f2tf32(bR0.y - __uint_as_float(uh.y));   \
            uh.z = f2tf32(bR0.z); ul.z = f2tf32(bR0.z - __uint_as_float(uh.z));   \
            uh.w = f2tf32(bR0.w); ul.w = f2tf32(bR0.w - __uint_as_float(uh.w));   \
            *(uint4*)&Bh[bRow * BSTRIDE + bC4] = uh;                              \
            *(uint4*)&Bl[bRow * BSTRIDE + bC4] = ul;                              \
            uh.x = f2tf32(bR1.x); ul.x = f2tf32(bR1.x - __uint_as_float(uh.x));   \
            uh.y = f2tf32(bR1.y); ul.y = f2tf32(bR1.y - __uint_as_float(uh.y));   \
            uh.z = f2tf32(bR1.z); ul.z = f2tf32(bR1.z - __uint_as_float(uh.z));   \
            uh.w = f2tf32(bR1.w); ul.w = f2tf32(bR1.w - __uint_as_float(uh.w));   \
            *(uint4*)&Bh[(bRow + 8) * BSTRIDE + bC4] = uh;                        \
            *(uint4*)&Bl[(bRow + 8) * BSTRIDE + bC4] = ul;                        \
        } while (0)

    const int NIT = K / GBK;

    LDG_TILE(0);
    STS_TILE(0);
    __syncthreads();

    for (int it = 0; it < NIT; it++) {
        const int cur = it & 1;
        if (it + 1 < NIT) LDG_TILE((it + 1) * GBK);

        const uint32_t* At = AsT + cur * A_BUF;
        const uint32_t* Bh = BsH + cur * B_BUF;
        const uint32_t* Bl = BsL + cur * B_BUF;

        #pragma unroll
        for (int kk = 0; kk < GBK; kk += 8) {
            uint32_t bh[4][2], bl[4][2];
            #pragma unroll
            for (int nt = 0; nt < 4; nt++) {
                int n0 = wn * 32 + nt * 8 + g;
                bh[nt][0] = Bh[(kk + r)     * BSTRIDE + n0];
                bh[nt][1] = Bh[(kk + r + 4) * BSTRIDE + n0];
                bl[nt][0] = Bl[(kk + r)     * BSTRIDE + n0];
                bl[nt][1] = Bl[(kk + r + 4) * BSTRIDE + n0];
            }
            #pragma unroll
            for (int mt = 0; mt < 4; mt++) {
                int m0 = wm * 64 + mt * 16 + g;
                uint32_t aH[4];
                aH[0] = At[m0       * ASTRIDE + kk + r];
                aH[1] = At[(m0 + 8) * ASTRIDE + kk + r];
                aH[2] = At[m0       * ASTRIDE + kk + r + 4];
                aH[3] = At[(m0 + 8) * ASTRIDE + kk + r + 4];
                #pragma unroll
                for (int nt = 0; nt < 4; nt++) {
                    mma_tf32(acc[mt][nt], aH, bl[nt]);
                    mma_tf32(acc[mt][nt], aH, bh[nt]);
                }
            }
        }

        if (it + 1 < NIT) STS_TILE(cur ^ 1);
        __syncthreads();
    }

    #pragma unroll
    for (int mt = 0; mt < 4; mt++) {
        int row0 = by * GBM + wm * 64 + mt * 16 + g;
        #pragma unroll
        for (int nt = 0; nt < 4; nt++) {
            int col = bx * GBN + wn * 32 + nt * 8 + r * 2;
            float b0 = 0.f, b1 = 0.f;
            if (bias != nullptr) { b0 = bias[col]; b1 = bias[col + 1]; }
            float2 v0 = make_float2(acc[mt][nt][0] + b0, acc[mt][nt][1] + b1);
            float2 v1 = make_float2(acc[mt][nt][2] + b0, acc[mt][nt][3] + b1);
            *(float2*)(C + (size_t)row0 * Nn + col)       = v0;
            *(float2*)(C + (size_t)(row0 + 8) * Nn + col) = v1;
        }
    }
}

// ======================= Tensor-core flash attention (Q in registers) =======================
#define AKT 64
#define QT  64
#define KS_STRIDE 68
#define VS_STRIDE 136

#define A_KS 0
#define A_VS (A_KS + AKT*KS_STRIDE)
#define A_CV (A_VS + AKT*VS_STRIDE)
#define A_TOT (A_CV + 32)
#define ATTN_SMEM_BYTES (A_TOT * 4)   // 52352 bytes

__global__ __launch_bounds__(128, 3)
void attn_tc_kernel(const float* __restrict__ qk, const float* __restrict__ vbuf,
                    const float* __restrict__ conv, float* __restrict__ out)
{
    extern __shared__ uint32_t smu[];
    uint32_t* Ks = smu + A_KS;
    uint32_t* Vs = smu + A_VS;
    float*    Cv = (float*)(smu + A_CV);

    const int tid  = threadIdx.x;
    const int lane = tid & 31;
    const int w    = tid >> 5;
    const int g    = lane >> 2;
    const int r    = lane & 3;
    const int h    = blockIdx.y;
    const int b    = blockIdx.z;
    const int i0   = blockIdx.x * QT;
    const uint32_t full = 0xffffffffu;

    if (tid < 2 * MAX_POS + 1) Cv[tid] = conv[h * (2 * MAX_POS + 1) + tid];

    // ---- Q fragments: loaded once, held in registers for all 32 j-tiles ----
    uint32_t qa[8][4];
    {
        const float* q0 = qk + (size_t)(b * N + i0 + w * 16 + g) * DIM + h * DQK;
        const float* q1 = q0 + 8 * DIM;
        #pragma unroll
        for (int kt = 0; kt < 8; kt++) {
            qa[kt][0] = f2tf32(q0[kt * 8 + r]);
            qa[kt][1] = f2tf32(q1[kt * 8 + r]);
            qa[kt][2] = f2tf32(q0[kt * 8 + r + 4]);
            qa[kt][3] = f2tf32(q1[kt * 8 + r + 4]);
        }
    }

    float m_lo = -CUDART_INF_F, m_hi = -CUDART_INF_F;
    float l_lo = 0.f, l_hi = 0.f;
    float oacc[8][2][4];
    #pragma unroll
    for (int mt = 0; mt < 8; mt++)
        #pragma unroll
        for (int nt = 0; nt < 2; nt++)
            #pragma unroll
            for (int i = 0; i < 4; i++) oacc[mt][nt][i] = 0.f;

    const int ilo = i0 + w * 16 + g;
    const int ihi = ilo + 8;
    const int srcA = (lane & ~3) | (r >> 1);
    const int srcB = srcA + 2;
    const bool pr  = (r & 1);

    for (int j0 = 0; j0 < N; j0 += AKT) {
        // ---- stage K (64x64) and V (64x128), tf32-rounded ----
        for (int t = tid; t < AKT * 16; t += 128) {
            int row = t >> 4, c4 = (t & 15) << 2;
            float4 v = *(const float4*)(qk + ((size_t)(b * N + j0 + row)) * DIM
                                         + HEADS * DQK + h * DQK + c4);
            uint4 u;
            u.x = f2tf32(v.x); u.y = f2tf32(v.y); u.z = f2tf32(v.z); u.w = f2tf32(v.w);
            *(uint4*)&Ks[row * KS_STRIDE + c4] = u;
        }
        for (int t = tid; t < AKT * 32; t += 128) {
            int row = t >> 5, c4 = (t & 31) << 2;
            float4 v = *(const float4*)(vbuf + ((size_t)(b * N + j0 + row)) * DIM + h * DV + c4);
            uint4 u;
            u.x = f2tf32(v.x); u.y = f2tf32(v.y); u.z = f2tf32(v.z); u.w = f2tf32(v.w);
            *(uint4*)&Vs[row * VS_STRIDE + c4] = u;
        }
        __syncthreads();

        // ---- S = Q K^T : per warp S[16, 64] ----
        float sacc[8][4];
        #pragma unroll
        for (int nt = 0; nt < 8; nt++)
            #pragma unroll
            for (int i = 0; i < 4; i++) sacc[nt][i] = 0.f;

        #pragma unroll
        for (int kt = 0; kt < 8; kt++) {
            #pragma unroll
            for (int nt = 0; nt < 8; nt++) {
                uint32_t bf[2];
                bf[0] = Ks[(nt * 8 + g) * KS_STRIDE + kt * 8 + r];
                bf[1] = Ks[(nt * 8 + g) * KS_STRIDE + kt * 8 + r + 4];
                mma_tf32(sacc[nt], qa[kt], bf);
            }
        }

        // ---- scale + relative-position bias + row max ----
        float rx_lo = -CUDART_INF_F, rx_hi = -CUDART_INF_F;
        #pragma unroll
        for (int nt = 0; nt < 8; nt++) {
            int j = j0 + nt * 8 + 2 * r;
            int d00 = min(max(j     - ilo, -MAX_POS), MAX_POS) + MAX_POS;
            int d01 = min(max(j + 1 - ilo, -MAX_POS), MAX_POS) + MAX_POS;
            int d10 = min(max(j     - ihi, -MAX_POS), MAX_POS) + MAX_POS;
            int d11 = min(max(j + 1 - ihi, -MAX_POS), MAX_POS) + MAX_POS;
            sacc[nt][0] = sacc[nt][0] * SCALE + Cv[d00];
            sacc[nt][1] = sacc[nt][1] * SCALE + Cv[d01];
            sacc[nt][2] = sacc[nt][2] * SCALE + Cv[d10];
            sacc[nt][3] = sacc[nt][3] * SCALE + Cv[d11];
            rx_lo = fmaxf(rx_lo, fmaxf(sacc[nt][0], sacc[nt][1]));
            rx_hi = fmaxf(rx_hi, fmaxf(sacc[nt][2], sacc[nt][3]));
        }
        rx_lo = fmaxf(rx_lo, __shfl_xor_sync(full, rx_lo, 1));
        rx_lo = fmaxf(rx_lo, __shfl_xor_sync(full, rx_lo, 2));
        rx_hi = fmaxf(rx_hi, __shfl_xor_sync(full, rx_hi, 1));
        rx_hi = fmaxf(rx_hi, __shfl_xor_sync(full, rx_hi, 2));

        float mn_lo = fmaxf(m_lo, rx_lo);
        float mn_hi = fmaxf(m_hi, rx_hi);
        float al_lo = __expf(m_lo - mn_lo);
        float al_hi = __expf(m_hi - mn_hi);
        m_lo = mn_lo; m_hi = mn_hi;

        // ---- exp -> P (tf32), partial row sums ----
        uint32_t Pf[8][4];
        float ls_lo = 0.f, ls_hi = 0.f;
        #pragma unroll
        for (int nt = 0; nt < 8; nt++) {
            float p0 = __expf(sacc[nt][0] - m_lo);
            float p1 = __expf(sacc[nt][1] - m_lo);
            float p2 = __expf(sacc[nt][2] - m_hi);
            float p3 = __expf(sacc[nt][3] - m_hi);
            ls_lo += p0 + p1;
            ls_hi += p2 + p3;
            Pf[nt][0] = f2tf32(p0); Pf[nt][1] = f2tf32(p1);
            Pf[nt][2] = f2tf32(p2); Pf[nt][3] = f2tf32(p3);
        }
        l_lo = l_lo * al_lo + ls_lo;
        l_hi = l_hi * al_hi + ls_hi;

        // ---- rescale out accumulators (alpha per q-column) ----
        float aq0  = __shfl_sync(full, al_lo, 8 * r);
        float aq1  = __shfl_sync(full, al_lo, 8 * r + 4);
        float aq0h = __shfl_sync(full, al_hi, 8 * r);
        float aq1h = __shfl_sync(full, al_hi, 8 * r + 4);
        #pragma unroll
        for (int mt = 0; mt < 8; mt++) {
            oacc[mt][0][0] *= aq0;  oacc[mt][0][1] *= aq1;
            oacc[mt][0][2] *= aq0;  oacc[mt][0][3] *= aq1;
            oacc[mt][1][0] *= aq0h; oacc[mt][1][1] *= aq1h;
            oacc[mt][1][2] *= aq0h; oacc[mt][1][3] *= aq1h;
        }

        // ---- (PV)^T = V^T P^T ----
        #pragma unroll
        for (int kt = 0; kt < 8; kt++) {
            uint32_t s0 = __shfl_sync(full, Pf[kt][0], srcA);
            uint32_t s1 = __shfl_sync(full, Pf[kt][1], srcA);
            uint32_t t0 = __shfl_sync(full, Pf[kt][0], srcB);
            uint32_t t1 = __shfl_sync(full, Pf[kt][1], srcB);
            uint32_t bl2[2];
            bl2[0] = pr ? s1 : s0;
            bl2[1] = pr ? t1 : t0;
            uint32_t s2 = __shfl_sync(full, Pf[kt][2], srcA);
            uint32_t s3 = __shfl_sync(full, Pf[kt][3], srcA);
            uint32_t t2 = __shfl_sync(full, Pf[kt][2], srcB);
            uint32_t t3 = __shfl_sync(full, Pf[kt][3], srcB);
            uint32_t bh2[2];
            bh2[0] = pr ? s3 : s2;
            bh2[1] = pr ? t3 : t2;
            #pragma unroll
            for (int mt = 0; mt < 8; mt++) {
                uint32_t vf[4];
                vf[0] = Vs[(kt * 8 + r)     * VS_STRIDE + mt * 16 + g];
                vf[1] = Vs[(kt * 8 + r)     * VS_STRIDE + mt * 16 + 8 + g];
                vf[2] = Vs[(kt * 8 + r + 4) * VS_STRIDE + mt * 16 + g];
                vf[3] = Vs[(kt * 8 + r + 4) * VS_STRIDE + mt * 16 + 8 + g];
                mma_tf32(oacc[mt][0], vf, bl2);
                mma_tf32(oacc[mt][1], vf, bh2);
            }
        }
        __syncthreads();
    }

    // ---- epilogue: normalize and write ----
    l_lo += __shfl_xor_sync(full, l_lo, 1);
    l_lo += __shfl_xor_sync(full, l_lo, 2);
    l_hi += __shfl_xor_sync(full, l_hi, 1);
    l_hi += __shfl_xor_sync(full, l_hi, 2);
    float inv_lo = 1.f / l_lo;
    float inv_hi = 1.f / l_hi;
    float iq0  = __shfl_sync(full, inv_lo, 8 * r);
    float iq1  = __shfl_sync(full, inv_lo, 8 * r + 4);
    float iq0h = __shfl_sync(full, inv_hi, 8 * r);
    float iq1h = __shfl_sync(full, inv_hi, 8 * r + 4);

    const size_t rbase = (size_t)(b * N + i0 + w * 16);
    #pragma unroll
    for (int mt = 0; mt < 8; mt++) {
        int dcol = h * DV + mt * 16 + g;
        out[(rbase + 2 * r    ) * DIM + dcol    ] = oacc[mt][0][0] * iq0;
        out[(rbase + 2 * r + 1) * DIM + dcol    ] = oacc[mt][0][1] * iq1;
        out[(rbase + 2 * r    ) * DIM + dcol + 8] = oacc[mt][0][2] * iq0;
        out[(rbase + 2 * r + 1) * DIM + dcol + 8] = oacc[mt][0][3] * iq1;
        out[(rbase + 8 + 2 * r    ) * DIM + dcol    ] = oacc[mt][1][0] * iq0h;
        out[(rbase + 8 + 2 * r + 1) * DIM + dcol    ] = oacc[mt][1][1] * iq1h;
        out[(rbase + 8 + 2 * r    ) * DIM + dcol + 8] = oacc[mt][1][2] * iq0h;
        out[(rbase + 8 + 2 * r + 1) * DIM + dcol + 8] = oacc[mt][1][3] * iq1h;
    }
}

// ======================= launch =======================
extern "C" void kernel_launch(void* const* d_in, const int* in_sizes, int n_in,
                              void* d_out, int out_size)
{
    const float* x     = (const float*)d_in[0];
    // d_in[1] = mask (unused by the reference)
    const float* W_qk  = (const float*)d_in[2];
    const float* W_v   = (const float*)d_in[3];
    const float* W_out = (const float*)d_in[4];
    const float* b_out = (const float*)d_in[5];
    const float* conv  = (const float*)d_in[6];
    float* out = (float*)d_out;

    float *qk_p, *v_p, *ao_p;
    cudaGetSymbolAddress((void**)&qk_p, g_qk);
    cudaGetSymbolAddress((void**)&v_p,  g_v);
    cudaGetSymbolAddress((void**)&ao_p, g_ao);

    cudaFuncSetAttribute(gemm2x_kernel, cudaFuncAttributeMaxDynamicSharedMemorySize,
                         GEMM_SMEM_BYTES);
    cudaFuncSetAttribute(attn_tc_kernel, cudaFuncAttributeMaxDynamicSharedMemorySize,
                         ATTN_SMEM_BYTES);

    // 1+2) fused: qk = x @ W_qk  and  v = x @ W_v  (shared A operand)
    dim3 qkv_grid(2 * DIM / GBN, BN_ROWS / GBM);   // (16, 64)
    gemm2x_kernel<<<qkv_grid, 256, GEMM_SMEM_BYTES>>>(
        x, W_qk, W_v, nullptr, qk_p, v_p, DIM / GBN, BN_ROWS, DIM, DIM);

    // 3) attention -> g_ao
    dim3 attn_grid(N / QT, HEADS, B);              // (32, 8, 4)
    attn_tc_kernel<<<attn_grid, 128, ATTN_SMEM_BYTES>>>(qk_p, v_p, conv, ao_p);

    // 4) out = g_ao @ W_out + b_out
    dim3 out_grid(DIM / GBN, BN_ROWS / GBM);       // (8, 64)
    gemm2x_kernel<<<out_grid, 256, GEMM_SMEM_BYTES>>>(
        ao_p, W_out, W_out, b_out, out, out, DIM / GBN, BN_ROWS, DIM, DIM);
}

// round 9
// speedup vs baseline: 1.2747x; 1.2175x over previous
#include <cuda_runtime.h>
#include <math_constants.h>
#include <stdint.h>

// Problem constants
#define B 4
#define N 2048
#define DIM 1024
#define HEADS 8
#define DQK 64
#define DV 128
#define MAX_POS 10
#define SCALE 0.125f   // 64^-0.5
#define BN_ROWS (B*N)  // 8192

// -------- scratch (device globals: allocation-free) --------
__device__ float g_qk[(size_t)BN_ROWS * DIM];  // q | k packed, tf32-rounded bits
__device__ float g_v [(size_t)BN_ROWS * DIM];  // tf32-rounded bits
__device__ float g_ao[(size_t)BN_ROWS * DIM];  // attention output (full f32)

// ---------------- tf32 helpers ----------------
__device__ __forceinline__ uint32_t f2tf32(float x) {
    uint32_t r;
    asm("cvt.rna.tf32.f32 %0, %1;" : "=r"(r) : "f"(x));
    return r;
}

__device__ __forceinline__ void mma_tf32(float c[4], const uint32_t a[4], const uint32_t b[2]) {
    asm volatile(
        "mma.sync.aligned.m16n8k8.row.col.f32.tf32.tf32.f32 "
        "{%0,%1,%2,%3}, {%4,%5,%6,%7}, {%8,%9}, {%0,%1,%2,%3};"
        : "+f"(c[0]), "+f"(c[1]), "+f"(c[2]), "+f"(c[3])
        : "r"(a[0]), "r"(a[1]), "r"(a[2]), "r"(a[3]), "r"(b[0]), "r"(b[1]));
}

__device__ __forceinline__ uint32_t smem_u32(const void* p) {
    uint32_t a;
    asm("{ .reg .u64 t; cvta.to.shared.u64 t, %1; cvt.u32.u64 %0, t; }" : "=r"(a) : "l"(p));
    return a;
}

// cp.async 16B, L1-bypass (cg)
__device__ __forceinline__ void cp16(uint32_t dst, const void* src) {
    asm volatile("cp.async.cg.shared.global [%0], [%1], 16;" :: "r"(dst), "l"(src) : "memory");
}
#define CP_COMMIT() asm volatile("cp.async.commit_group;" ::: "memory")
#define CP_WAIT1()  asm volatile("cp.async.wait_group 1;" ::: "memory")
#define CP_WAIT0()  asm volatile("cp.async.wait_group 0;" ::: "memory")

// ======================= 2xTF32 tensor-core GEMM, double-buffered =======================
#define GBM 128
#define GBN 128
#define GBK 16
#define ASTRIDE 20
#define BSTRIDE 136
#define A_BUF (GBM*ASTRIDE)
#define B_BUF (GBK*BSTRIDE)
#define GEMM_SMEM_WORDS (2*A_BUF + 4*B_BUF)
#define GEMM_SMEM_BYTES (GEMM_SMEM_WORDS*4)   // 55296

__global__ __launch_bounds__(256, 2)
void gemm2x_kernel(const float* __restrict__ A,
                   const float* __restrict__ B0, const float* __restrict__ B1,
                   const float* __restrict__ bias,
                   float* __restrict__ C0, float* __restrict__ C1,
                   int nx, int round_c, int M, int Nn, int K)
{
    extern __shared__ uint32_t smg[];
    uint32_t* AsT = smg;
    uint32_t* BsH = smg + 2 * A_BUF;
    uint32_t* BsL = smg + 2 * A_BUF + 2 * B_BUF;

    const int tid  = threadIdx.x;
    const int lane = tid & 31;
    const int w    = tid >> 5;
    const int wm   = w >> 2;
    const int wn   = w & 3;
    const int g    = lane >> 2;
    const int r    = lane & 3;

    int bx = blockIdx.x;
    const int by = blockIdx.y;
    const float* Bm = B0;
    float* C = C0;
    if (bx >= nx) { Bm = B1; C = C1; bx -= nx; }

    const float* Ablk = A  + (size_t)(by * GBM) * K;
    const float* Bblk = Bm + (size_t)(bx * GBN);

    const int aRow = tid >> 2;
    const int aC4  = (tid & 3) << 2;
    const int bRow = tid >> 5;
    const int bC4  = (tid & 31) << 2;

    float acc[4][4][4];
    #pragma unroll
    for (int mt = 0; mt < 4; mt++)
        #pragma unroll
        for (int nt = 0; nt < 4; nt++)
            #pragma unroll
            for (int i = 0; i < 4; i++) acc[mt][nt][i] = 0.f;

    float4 aR0, aR1, bR0, bR1;

    #define LDG_TILE(k0)                                                          \
        do {                                                                      \
            aR0 = *(const float4*)(Ablk + (size_t)aRow * K + (k0) + aC4);         \
            aR1 = *(const float4*)(Ablk + (size_t)(aRow + 64) * K + (k0) + aC4);  \
            bR0 = *(const float4*)(Bblk + (size_t)((k0) + bRow) * Nn + bC4);      \
            bR1 = *(const float4*)(Bblk + (size_t)((k0) + bRow + 8) * Nn + bC4);  \
        } while (0)

    #define STS_TILE(buf)                                                         \
        do {                                                                      \
            uint32_t* At = AsT + (buf) * A_BUF;                                   \
            uint32_t* Bh = BsH + (buf) * B_BUF;                                   \
            uint32_t* Bl = BsL + (buf) * B_BUF;                                   \
            uint4 u;                                                              \
            u.x = f2tf32(aR0.x); u.y = f2tf32(aR0.y);                             \
            u.z = f2tf32(aR0.z); u.w = f2tf32(aR0.w);                             \
            *(uint4*)&At[aRow * ASTRIDE + aC4] = u;                               \
            u.x = f2tf32(aR1.x); u.y = f2tf32(aR1.y);                             \
            u.z = f2tf32(aR1.z); u.w = f2tf32(aR1.w);                             \
            *(uint4*)&At[(aRow + 64) * ASTRIDE + aC4] = u;                        \
            uint4 uh, ul;                                                         \
            uh.x = f2tf32(bR0.x); ul.x = f2tf32(bR0.x - __uint_as_float(uh.x));   \
            uh.y = f2tf32(bR0.y); ul.y = f2tf32(bR0.y - __uint_as_float(uh.y));   \
            uh.z = f2tf32(bR0.z); ul.z = f2tf32(bR0.z - __uint_as_float(uh.z));   \
            uh.w = f2tf32(bR0.w); ul.w = f2tf32(bR0.w - __uint_as_float(uh.w));   \
            *(uint4*)&Bh[bRow * BSTRIDE + bC4] = uh;                              \
            *(uint4*)&Bl[bRow * BSTRIDE + bC4] = ul;                              \
            uh.x = f2tf32(bR1.x); ul.x = f2tf32(bR1.x - __uint_as_float(uh.x));   \
            uh.y = f2tf32(bR1.y); ul.y = f2tf32(bR1.y - __uint_as_float(uh.y));   \
            uh.z = f2tf32(bR1.z); ul.z = f2tf32(bR1.z - __uint_as_float(uh.z));   \
            uh.w = f2tf32(bR1.w); ul.w = f2tf32(bR1.w - __uint_as_float(uh.w));   \
            *(uint4*)&Bh[(bRow + 8) * BSTRIDE + bC4] = uh;                        \
            *(uint4*)&Bl[(bRow + 8) * BSTRIDE + bC4] = ul;                        \
        } while (0)

    const int NIT = K / GBK;

    LDG_TILE(0);
    STS_TILE(0);
    __syncthreads();

    for (int it = 0; it < NIT; it++) {
        const int cur = it & 1;
        if (it + 1 < NIT) LDG_TILE((it + 1) * GBK);

        const uint32_t* At = AsT + cur * A_BUF;
        const uint32_t* Bh = BsH + cur * B_BUF;
        const uint32_t* Bl = BsL + cur * B_BUF;

        #pragma unroll
        for (int kk = 0; kk < GBK; kk += 8) {
            uint32_t bh[4][2], bl[4][2];
            #pragma unroll
            for (int nt = 0; nt < 4; nt++) {
                int n0 = wn * 32 + nt * 8 + g;
                bh[nt][0] = Bh[(kk + r)     * BSTRIDE + n0];
                bh[nt][1] = Bh[(kk + r + 4) * BSTRIDE + n0];
                bl[nt][0] = Bl[(kk + r)     * BSTRIDE + n0];
                bl[nt][1] = Bl[(kk + r + 4) * BSTRIDE + n0];
            }
            #pragma unroll
            for (int mt = 0; mt < 4; mt++) {
                int m0 = wm * 64 + mt * 16 + g;
                uint32_t aH[4];
                aH[0] = At[m0       * ASTRIDE + kk + r];
                aH[1] = At[(m0 + 8) * ASTRIDE + kk + r];
                aH[2] = At[m0       * ASTRIDE + kk + r + 4];
                aH[3] = At[(m0 + 8) * ASTRIDE + kk + r + 4];
                #pragma unroll
                for (int nt = 0; nt < 4; nt++) {
                    mma_tf32(acc[mt][nt], aH, bl[nt]);
                    mma_tf32(acc[mt][nt], aH, bh[nt]);
                }
            }
        }

        if (it + 1 < NIT) STS_TILE(cur ^ 1);
        __syncthreads();
    }

    #pragma unroll
    for (int mt = 0; mt < 4; mt++) {
        int row0 = by * GBM + wm * 64 + mt * 16 + g;
        #pragma unroll
        for (int nt = 0; nt < 4; nt++) {
            int col = bx * GBN + wn * 32 + nt * 8 + r * 2;
            float b0 = 0.f, b1 = 0.f;
            if (bias != nullptr) { b0 = bias[col]; b1 = bias[col + 1]; }
            float2 v0 = make_float2(acc[mt][nt][0] + b0, acc[mt][nt][1] + b1);
            float2 v1 = make_float2(acc[mt][nt][2] + b0, acc[mt][nt][3] + b1);
            if (round_c) {
                v0.x = __uint_as_float(f2tf32(v0.x));
                v0.y = __uint_as_float(f2tf32(v0.y));
                v1.x = __uint_as_float(f2tf32(v1.x));
                v1.y = __uint_as_float(f2tf32(v1.y));
            }
            *(float2*)(C + (size_t)row0 * Nn + col)       = v0;
            *(float2*)(C + (size_t)(row0 + 8) * Nn + col) = v1;
        }
    }
}

// ======================= Tensor-core flash attention (cp.async double-buffered) ========
// Inputs qk/v hold tf32-rounded bits: staging is a raw byte copy.
#define AKT 64
#define QT  64
#define KS_W 68                      // K row stride (words)
#define VS_W 136                     // V row stride (words)
#define KS_BYTES (AKT * KS_W * 4)    // 17408
#define VS_BYTES (AKT * VS_W * 4)    // 34816
#define BUF_BYTES (KS_BYTES + VS_BYTES)   // 52224
#define BUF_WORDS (BUF_BYTES / 4)
#define ATTN_SMEM_BYTES (2 * BUF_BYTES + 128)   // 104576

__global__ __launch_bounds__(128, 2)
void attn_tc_kernel(const float* __restrict__ qk, const float* __restrict__ vbuf,
                    const float* __restrict__ conv, float* __restrict__ out)
{
    extern __shared__ uint32_t smu[];
    float* Cv = (float*)(smu + 2 * BUF_WORDS);
    const uint32_t sbase = smem_u32(smu);

    const int tid  = threadIdx.x;
    const int lane = tid & 31;
    const int w    = tid >> 5;
    const int g    = lane >> 2;
    const int r    = lane & 3;
    const int h    = blockIdx.y;
    const int b    = blockIdx.z;
    const int i0   = blockIdx.x * QT;
    const uint32_t full = 0xffffffffu;

    if (tid < 2 * MAX_POS + 1) Cv[tid] = conv[h * (2 * MAX_POS + 1) + tid];

    // ---- Q fragments: pre-rounded bits, loaded once ----
    uint32_t qa[8][4];
    {
        const uint32_t* q0 = (const uint32_t*)(qk + (size_t)(b * N + i0 + w * 16 + g) * DIM + h * DQK);
        const uint32_t* q1 = q0 + 8 * DIM;
        #pragma unroll
        for (int kt = 0; kt < 8; kt++) {
            qa[kt][0] = q0[kt * 8 + r];
            qa[kt][1] = q1[kt * 8 + r];
            qa[kt][2] = q0[kt * 8 + r + 4];
            qa[kt][3] = q1[kt * 8 + r + 4];
        }
    }

    // ---- async stage of K/V tile j0 into buffer bb ----
    #define STAGE(j0v, bb)                                                        \
        do {                                                                      \
            uint32_t kb = sbase + (bb) * BUF_BYTES;                               \
            const float* ks = qk + (size_t)(b * N + (j0v)) * DIM                  \
                              + HEADS * DQK + h * DQK;                            \
            _Pragma("unroll")                                                     \
            for (int i = 0; i < 8; i++) {                                         \
                int idx = tid + 128 * i;                                          \
                int row = idx >> 4, c4 = (idx & 15) << 2;                         \
                cp16(kb + (uint32_t)(row * KS_W + c4) * 4,                        \
                     ks + (size_t)row * DIM + c4);                                \
            }                                                                     \
            uint32_t vb = kb + KS_BYTES;                                          \
            const float* vs = vbuf + (size_t)(b * N + (j0v)) * DIM + h * DV;      \
            _Pragma("unroll")                                                     \
            for (int i = 0; i < 16; i++) {                                        \
                int idx = tid + 128 * i;                                          \
                int row = idx >> 5, c4 = (idx & 31) << 2;                         \
                cp16(vb + (uint32_t)(row * VS_W + c4) * 4,                        \
                     vs + (size_t)row * DIM + c4);                                \
            }                                                                     \
            CP_COMMIT();                                                          \
        } while (0)

    float m_lo = -CUDART_INF_F, m_hi = -CUDART_INF_F;
    float l_lo = 0.f, l_hi = 0.f;
    float oacc[8][2][4];
    #pragma unroll
    for (int mt = 0; mt < 8; mt++)
        #pragma unroll
        for (int nt = 0; nt < 2; nt++)
            #pragma unroll
            for (int i = 0; i < 4; i++) oacc[mt][nt][i] = 0.f;

    const int ilo = i0 + w * 16 + g;
    const int ihi = ilo + 8;
    const int srcA = (lane & ~3) | (r >> 1);
    const int srcB = srcA + 2;
    const bool pr  = (r & 1);

    STAGE(0, 0);

    const int NJ = N / AKT;   // 32
    for (int jt = 0; jt < NJ; jt++) {
        const int buf = jt & 1;
        if (jt + 1 < NJ) { STAGE((jt + 1) * AKT, buf ^ 1); CP_WAIT1(); }
        else             { CP_WAIT0(); }
        __syncthreads();

        const uint32_t* Ks = smu + buf * BUF_WORDS;
        const uint32_t* Vs = Ks + KS_BYTES / 4;
        const int j0 = jt * AKT;

        // ---- S = Q K^T : per warp S[16, 64] ----
        float sacc[8][4];
        #pragma unroll
        for (int nt = 0; nt < 8; nt++)
            #pragma unroll
            for (int i = 0; i < 4; i++) sacc[nt][i] = 0.f;

        #pragma unroll
        for (int kt = 0; kt < 8; kt++) {
            #pragma unroll
            for (int nt = 0; nt < 8; nt++) {
                uint32_t bf[2];
                bf[0] = Ks[(nt * 8 + g) * KS_W + kt * 8 + r];
                bf[1] = Ks[(nt * 8 + g) * KS_W + kt * 8 + r + 4];
                mma_tf32(sacc[nt], qa[kt], bf);
            }
        }

        // ---- scale + relative-position bias + row max ----
        float rx_lo = -CUDART_INF_F, rx_hi = -CUDART_INF_F;
        #pragma unroll
        for (int nt = 0; nt < 8; nt++) {
            int j = j0 + nt * 8 + 2 * r;
            int d00 = min(max(j     - ilo, -MAX_POS), MAX_POS) + MAX_POS;
            int d01 = min(max(j + 1 - ilo, -MAX_POS), MAX_POS) + MAX_POS;
            int d10 = min(max(j     - ihi, -MAX_POS), MAX_POS) + MAX_POS;
            int d11 = min(max(j + 1 - ihi, -MAX_POS), MAX_POS) + MAX_POS;
            sacc[nt][0] = sacc[nt][0] * SCALE + Cv[d00];
            sacc[nt][1] = sacc[nt][1] * SCALE + Cv[d01];
            sacc[nt][2] = sacc[nt][2] * SCALE + Cv[d10];
            sacc[nt][3] = sacc[nt][3] * SCALE + Cv[d11];
            rx_lo = fmaxf(rx_lo, fmaxf(sacc[nt][0], sacc[nt][1]));
            rx_hi = fmaxf(rx_hi, fmaxf(sacc[nt][2], sacc[nt][3]));
        }
        rx_lo = fmaxf(rx_lo, __shfl_xor_sync(full, rx_lo, 1));
        rx_lo = fmaxf(rx_lo, __shfl_xor_sync(full, rx_lo, 2));
        rx_hi = fmaxf(rx_hi, __shfl_xor_sync(full, rx_hi, 1));
        rx_hi = fmaxf(rx_hi, __shfl_xor_sync(full, rx_hi, 2));

        float mn_lo = fmaxf(m_lo, rx_lo);
        float mn_hi = fmaxf(m_hi, rx_hi);
        float al_lo = __expf(m_lo - mn_lo);
        float al_hi = __expf(m_hi - mn_hi);
        m_lo = mn_lo; m_hi = mn_hi;

        // ---- exp -> P (tf32), partial row sums ----
        uint32_t Pf[8][4];
        float ls_lo = 0.f, ls_hi = 0.f;
        #pragma unroll
        for (int nt = 0; nt < 8; nt++) {
            float p0 = __expf(sacc[nt][0] - m_lo);
            float p1 = __expf(sacc[nt][1] - m_lo);
            float p2 = __expf(sacc[nt][2] - m_hi);
            float p3 = __expf(sacc[nt][3] - m_hi);
            ls_lo += p0 + p1;
            ls_hi += p2 + p3;
            Pf[nt][0] = f2tf32(p0); Pf[nt][1] = f2tf32(p1);
            Pf[nt][2] = f2tf32(p2); Pf[nt][3] = f2tf32(p3);
        }
        l_lo = l_lo * al_lo + ls_lo;
        l_hi = l_hi * al_hi + ls_hi;

        // ---- rescale out accumulators ----
        float aq0  = __shfl_sync(full, al_lo, 8 * r);
        float aq1  = __shfl_sync(full, al_lo, 8 * r + 4);
        float aq0h = __shfl_sync(full, al_hi, 8 * r);
        float aq1h = __shfl_sync(full, al_hi, 8 * r + 4);
        #pragma unroll
        for (int mt = 0; mt < 8; mt++) {
            oacc[mt][0][0] *= aq0;  oacc[mt][0][1] *= aq1;
            oacc[mt][0][2] *= aq0;  oacc[mt][0][3] *= aq1;
            oacc[mt][1][0] *= aq0h; oacc[mt][1][1] *= aq1h;
            oacc[mt][1][2] *= aq0h; oacc[mt][1][3] *= aq1h;
        }

        // ---- (PV)^T = V^T P^T ----
        #pragma unroll
        for (int kt = 0; kt < 8; kt++) {
            uint32_t s0 = __shfl_sync(full, Pf[kt][0], srcA);
            uint32_t s1 = __shfl_sync(full, Pf[kt][1], srcA);
            uint32_t t0 = __shfl_sync(full, Pf[kt][0], srcB);
            uint32_t t1 = __shfl_sync(full, Pf[kt][1], srcB);
            uint32_t bl2[2];
            bl2[0] = pr ? s1 : s0;
            bl2[1] = pr ? t1 : t0;
            uint32_t s2 = __shfl_sync(full, Pf[kt][2], srcA);
            uint32_t s3 = __shfl_sync(full, Pf[kt][3], srcA);
            uint32_t t2 = __shfl_sync(full, Pf[kt][2], srcB);
            uint32_t t3 = __shfl_sync(full, Pf[kt][3], srcB);
            uint32_t bh2[2];
            bh2[0] = pr ? s3 : s2;
            bh2[1] = pr ? t3 : t2;
            #pragma unroll
            for (int mt = 0; mt < 8; mt++) {
                uint32_t vf[4];
                vf[0] = Vs[(kt * 8 + r)     * VS_W + mt * 16 + g];
                vf[1] = Vs[(kt * 8 + r)     * VS_W + mt * 16 + 8 + g];
                vf[2] = Vs[(kt * 8 + r + 4) * VS_W + mt * 16 + g];
                vf[3] = Vs[(kt * 8 + r + 4) * VS_W + mt * 16 + 8 + g];
                mma_tf32(oacc[mt][0], vf, bl2);
                mma_tf32(oacc[mt][1], vf, bh2);
            }
        }
        __syncthreads();
    }

    // ---- epilogue: normalize and write ----
    l_lo += __shfl_xor_sync(full, l_lo, 1);
    l_lo += __shfl_xor_sync(full, l_lo, 2);
    l_hi += __shfl_xor_sync(full, l_hi, 1);
    l_hi += __shfl_xor_sync(full, l_hi, 2);
    float inv_lo = 1.f / l_lo;
    float inv_hi = 1.f / l_hi;
    float iq0  = __shfl_sync(full, inv_lo, 8 * r);
    float iq1  = __shfl_sync(full, inv_lo, 8 * r + 4);
    float iq0h = __shfl_sync(full, inv_hi, 8 * r);
    float iq1h = __shfl_sync(full, inv_hi, 8 * r + 4);

    const size_t rbase = (size_t)(b * N + i0 + w * 16);
    #pragma unroll
    for (int mt = 0; mt < 8; mt++) {
        int dcol = h * DV + mt * 16 + g;
        out[(rbase + 2 * r    ) * DIM + dcol    ] = oacc[mt][0][0] * iq0;
        out[(rbase + 2 * r + 1) * DIM + dcol    ] = oacc[mt][0][1] * iq1;
        out[(rbase + 2 * r    ) * DIM + dcol + 8] = oacc[mt][0][2] * iq0;
        out[(rbase + 2 * r + 1) * DIM + dcol + 8] = oacc[mt][0][3] * iq1;
        out[(rbase + 8 + 2 * r    ) * DIM + dcol    ] = oacc[mt][1][0] * iq0h;
        out[(rbase + 8 + 2 * r + 1) * DIM + dcol    ] = oacc[mt][1][1] * iq1h;
        out[(rbase + 8 + 2 * r    ) * DIM + dcol + 8] = oacc[mt][1][2] * iq0h;
        out[(rbase + 8 + 2 * r + 1) * DIM + dcol + 8] = oacc[mt][1][3] * iq1h;
    }
}

// ======================= launch =======================
extern "C" void kernel_launch(void* const* d_in, const int* in_sizes, int n_in,
                              void* d_out, int out_size)
{
    const float* x     = (const float*)d_in[0];
    // d_in[1] = mask (unused by the reference)
    const float* W_qk  = (const float*)d_in[2];
    const float* W_v   = (const float*)d_in[3];
    const float* W_out = (const float*)d_in[4];
    const float* b_out = (const float*)d_in[5];
    const float* conv  = (const float*)d_in[6];
    float* out = (float*)d_out;

    float *qk_p, *v_p, *ao_p;
    cudaGetSymbolAddress((void**)&qk_p, g_qk);
    cudaGetSymbolAddress((void**)&v_p,  g_v);
    cudaGetSymbolAddress((void**)&ao_p, g_ao);

    cudaFuncSetAttribute(gemm2x_kernel, cudaFuncAttributeMaxDynamicSharedMemorySize,
                         GEMM_SMEM_BYTES);
    cudaFuncSetAttribute(attn_tc_kernel, cudaFuncAttributeMaxDynamicSharedMemorySize,
                         ATTN_SMEM_BYTES);

    // 1+2) fused: qk = x @ W_qk and v = x @ W_v, outputs tf32-rounded
    dim3 qkv_grid(2 * DIM / GBN, BN_ROWS / GBM);   // (16, 64)
    gemm2x_kernel<<<qkv_grid, 256, GEMM_SMEM_BYTES>>>(
        x, W_qk, W_v, nullptr, qk_p, v_p, DIM / GBN, 1, BN_ROWS, DIM, DIM);

    // 3) attention -> g_ao
    dim3 attn_grid(N / QT, HEADS, B);              // (32, 8, 4)
    attn_tc_kernel<<<attn_grid, 128, ATTN_SMEM_BYTES>>>(qk_p, v_p, conv, ao_p);

    // 4) out = g_ao @ W_out + b_out (full precision output)
    dim3 out_grid(DIM / GBN, BN_ROWS / GBM);       // (8, 64)
    gemm2x_kernel<<<out_grid, 256, GEMM_SMEM_BYTES>>>(
        ao_p, W_out, W_out, b_out, out, out, DIM / GBN, 0, BN_ROWS, DIM, DIM);
}